// round 2
// baseline (speedup 1.0000x reference)
#include <cuda_runtime.h>

#define NB 256        // batch N
#define IN_F 1024
#define B_EXTRA 256
#define KDIM 16
#define OUT_F 1280
#define JDIM (B_EXTRA * KDIM)   // 4096

typedef unsigned long long u64;

// Split-K partial buffers for M = x @ W  (each 256 x 4096 f32 = 4 MB)
__device__ float g_M[NB * JDIM];
__device__ float g_M2[NB * JDIM];

// ---------------- f32x2 packed-math helpers (sm_103a FFMA2 path) -----------
__device__ __forceinline__ u64 pack2(float lo, float hi) {
    u64 d; asm("mov.b64 %0, {%1, %2};" : "=l"(d) : "f"(lo), "f"(hi)); return d;
}
__device__ __forceinline__ u64 dup2(unsigned r) {
    u64 d; asm("mov.b64 %0, {%1, %1};" : "=l"(d) : "r"(r)); return d;
}
__device__ __forceinline__ void ffma2(u64& d, u64 a, u64 b) {
    asm("fma.rn.f32x2 %0, %1, %2, %0;" : "+l"(d) : "l"(a), "l"(b));
}
__device__ __forceinline__ u64 add2(u64 a, u64 b) {
    u64 d; asm("add.rn.f32x2 %0, %1, %2;" : "=l"(d) : "l"(a), "l"(b)); return d;
}
__device__ __forceinline__ float lo2(u64 v) { return __uint_as_float((unsigned)v); }
__device__ __forceinline__ float hi2(u64 v) { return __uint_as_float((unsigned)(v >> 32)); }

// ---------------------------------------------------------------------------
// Kernel 1: SGEMM  M(256x4096) = x(256x1024) @ W(1024x4096), packed FFMA2.
// BM=64, BN=128, BK=16, 128 threads, 8x8 microtile (rows packed in f32x2),
// split-K=2 (blockIdx.z) into g_M / g_M2.
// ---------------------------------------------------------------------------
#define BMg 64
#define BNg 128
#define BKg 16
#define KSPLIT 512   // IN_F / 2

__global__ __launch_bounds__(128) void gemm_kernel(const float* __restrict__ x,
                                                   const float* __restrict__ W) {
    __shared__ float As[BKg][BMg + 2];   // stride 66 (even -> 8B-aligned pairs)
    __shared__ float Bs[BKg][BNg];

    const int bn = blockIdx.x;   // 0..31
    const int bm = blockIdx.y;   // 0..3
    const int kz = blockIdx.z;   // 0..1
    const int tid = threadIdx.x;
    const int tx = tid & 15;     // col group: 8 cols each
    const int ty = tid >> 4;     // row group: 8 rows each (4 packed pairs)

    const float* xg = x + (bm * BMg) * IN_F + kz * KSPLIT;
    const float* Wg = W + (size_t)(kz * KSPLIT) * JDIM + bn * BNg;
    float* Mout = kz ? g_M2 : g_M;

    u64 acc[4][8] = {};   // [rowpair][col], each = (row2i, row2i+1) packed

    const int r = tid & 63;        // A-load row
    const int kh = (tid >> 6) * 8; // A-load k half

    for (int k0 = 0; k0 < KSPLIT; k0 += BKg) {
        // A tile: 64 rows x 16 k -> As[k][row] (transposed)
        {
            const float* src = xg + r * IN_F + k0 + kh;
            float4 v0 = *(const float4*)src;
            float4 v1 = *(const float4*)(src + 4);
            As[kh + 0][r] = v0.x; As[kh + 1][r] = v0.y;
            As[kh + 2][r] = v0.z; As[kh + 3][r] = v0.w;
            As[kh + 4][r] = v1.x; As[kh + 5][r] = v1.y;
            As[kh + 6][r] = v1.z; As[kh + 7][r] = v1.w;
        }
        // B tile: 16 k x 128 cols, 4 float4 per thread
        {
#pragma unroll
            for (int p = 0; p < 4; p++) {
                const int i = tid * 4 + p;       // 0..511
                const int kr = i >> 5;
                const int c4 = i & 31;
                *(float4*)&Bs[kr][c4 * 4] =
                    *(const float4*)(Wg + (size_t)(k0 + kr) * JDIM + c4 * 4);
            }
        }
        __syncthreads();

#pragma unroll
        for (int k = 0; k < BKg; k++) {
            u64 a2[4];
#pragma unroll
            for (int i = 0; i < 4; i++)
                a2[i] = *(const u64*)&As[k][ty * 8 + 2 * i];
            u64 b2[8];
#pragma unroll
            for (int j = 0; j < 4; j++) {
                uint2 bp = *(const uint2*)&Bs[k][tx * 8 + 2 * j];
                b2[2 * j]     = dup2(bp.x);
                b2[2 * j + 1] = dup2(bp.y);
            }
#pragma unroll
            for (int i = 0; i < 4; i++)
#pragma unroll
                for (int j = 0; j < 8; j++)
                    ffma2(acc[i][j], a2[i], b2[j]);
        }
        __syncthreads();
    }

    // Epilogue: 8 rows x 8 cols per thread, 2 float4 stores per row.
    float* dst = Mout + (size_t)(bm * BMg + ty * 8) * JDIM + bn * BNg + tx * 8;
#pragma unroll
    for (int i = 0; i < 4; i++) {
        float4 vlo0 = make_float4(lo2(acc[i][0]), lo2(acc[i][1]), lo2(acc[i][2]), lo2(acc[i][3]));
        float4 vlo1 = make_float4(lo2(acc[i][4]), lo2(acc[i][5]), lo2(acc[i][6]), lo2(acc[i][7]));
        float4 vhi0 = make_float4(hi2(acc[i][0]), hi2(acc[i][1]), hi2(acc[i][2]), hi2(acc[i][3]));
        float4 vhi1 = make_float4(hi2(acc[i][4]), hi2(acc[i][5]), hi2(acc[i][6]), hi2(acc[i][7]));
        *(float4*)(dst + (size_t)(2 * i) * JDIM)     = vlo0;
        *(float4*)(dst + (size_t)(2 * i) * JDIM + 4) = vlo1;
        *(float4*)(dst + (size_t)(2 * i + 1) * JDIM)     = vhi0;
        *(float4*)(dst + (size_t)(2 * i + 1) * JDIM + 4) = vhi1;
    }
}

// ---------------------------------------------------------------------------
// Kernel 2: pairwise L1 + exp-sum (packed f32x2, two samples per iteration)
// + reduction of the two split-K partials + x-copy (folded in).
// Grid = 256 blocks (one per b), 256 threads (one per sample m).
// ---------------------------------------------------------------------------
__global__ __launch_bounds__(256) void pairwise_kernel(const float* __restrict__ x,
                                                       float* __restrict__ out) {
    __shared__ float sMt[KDIM][NB];   // transposed: sMt[k][n]

    const int b = blockIdx.x;
    const int tid = threadIdx.x;

    // Folded x-copy: exactly one float4 per thread (256*256 = 65536 float4s).
    {
        const int g = b * 256 + tid;
        const int row = g >> 8;
        const int c = g & 255;
        ((float4*)(out + (size_t)row * OUT_F))[c] =
            ((const float4*)(x + (size_t)row * IN_F))[c];
    }

    // Load M[:, b, :] = g_M + g_M2, store transposed.
    {
        const float4* A4 = (const float4*)(g_M + (size_t)tid * JDIM + b * KDIM);
        const float4* B4 = (const float4*)(g_M2 + (size_t)tid * JDIM + b * KDIM);
#pragma unroll
        for (int q = 0; q < 4; q++) {
            float4 u = A4[q], v = B4[q];
            sMt[4 * q + 0][tid] = u.x + v.x;
            sMt[4 * q + 1][tid] = u.y + v.y;
            sMt[4 * q + 2][tid] = u.z + v.z;
            sMt[4 * q + 3][tid] = u.w + v.w;
        }
    }
    __syncthreads();

    // My vector, pre-negated and duplicated into both f32x2 lanes.
    u64 negmy[KDIM];
#pragma unroll
    for (int k = 0; k < KDIM; k++) {
        float m = sMt[k][tid];
        negmy[k] = pack2(-m, -m);
    }

    const u64 ABSMASK = 0x7FFFFFFF7FFFFFFFULL;
    float acc = 0.0f;

#pragma unroll 2
    for (int p = 0; p < NB / 2; p++) {
        u64 l1a = 0, l1b = 0;   // two chains to break the 4-cyc dep chain
#pragma unroll
        for (int k = 0; k < KDIM; k += 2) {
            u64 m0 = *(const u64*)&sMt[k][2 * p];
            u64 m1 = *(const u64*)&sMt[k + 1][2 * p];
            u64 d0 = add2(m0, negmy[k]) & ABSMASK;
            u64 d1 = add2(m1, negmy[k + 1]) & ABSMASK;
            l1a = add2(l1a, d0);
            l1b = add2(l1b, d1);
        }
        u64 l1 = add2(l1a, l1b);   // (l1 for n=2p, l1 for n=2p+1)
        acc += __expf(-lo2(l1)) + __expf(-hi2(l1));
    }

    // self term exp(0)=1 subtracted per reference.
    out[(size_t)tid * OUT_F + IN_F + b] = acc - 1.0f;
}

extern "C" void kernel_launch(void* const* d_in, const int* in_sizes, int n_in,
                              void* d_out, int out_size) {
    const float* x = (const float*)d_in[0];   // (256, 1024)
    const float* T = (const float*)d_in[1];   // (1024, 256, 16) == W(1024, 4096)
    float* out = (float*)d_out;               // (256, 1280)

    dim3 gemm_grid(JDIM / BNg, NB / BMg, 2);  // (32, 4, 2) = 256 blocks
    gemm_kernel<<<gemm_grid, 128>>>(x, T);

    pairwise_kernel<<<B_EXTRA, NB>>>(x, out);
}

// round 4
// speedup vs baseline: 1.6419x; 1.6419x over previous
#include <cuda_runtime.h>
#include <cuda_bf16.h>
#include <cstdint>

#define NB 256
#define IN_F 1024
#define B_EXTRA 256
#define KDIM 16
#define OUT_F 1280
#define JDIM 4096            // B_EXTRA * KDIM

// ---------------- device scratch ----------------
__device__ float g_M[NB * JDIM];                        // 4 MB
__device__ __nv_bfloat16 g_xh[NB * IN_F];               // [m][k]
__device__ __nv_bfloat16 g_xl[NB * IN_F];
__device__ __nv_bfloat16 g_Wh[(size_t)IN_F * JDIM];     // [k][n] (native layout)
__device__ __nv_bfloat16 g_Wl[(size_t)IN_F * JDIM];

// ---------------- helpers ----------------
__device__ __forceinline__ uint32_t smem_u32(const void* p) {
    uint32_t a;
    asm("{ .reg .u64 t; cvta.to.shared.u64 t, %1; cvt.u32.u64 %0, t; }" : "=r"(a) : "l"(p));
    return a;
}
#define SWZ(x) ((x) ^ (((x) >> 3) & 0x70))

__device__ __forceinline__ void cp16(uint32_t dst, const void* src) {
    asm volatile("cp.async.cg.shared.global [%0], [%1], 16;" :: "r"(dst), "l"(src) : "memory");
}
#define CP_COMMIT() asm volatile("cp.async.commit_group;" ::: "memory")
#define CP_WAIT1()  asm volatile("cp.async.wait_group 1;" ::: "memory")

__device__ __forceinline__ void ldsm_x4(uint32_t* r, uint32_t a) {
    asm volatile("ldmatrix.sync.aligned.m8n8.x4.shared.b16 {%0,%1,%2,%3}, [%4];"
        : "=r"(r[0]), "=r"(r[1]), "=r"(r[2]), "=r"(r[3]) : "r"(a));
}
__device__ __forceinline__ void ldsm_x4_t(uint32_t* r, uint32_t a) {
    asm volatile("ldmatrix.sync.aligned.m8n8.x4.trans.shared.b16 {%0,%1,%2,%3}, [%4];"
        : "=r"(r[0]), "=r"(r[1]), "=r"(r[2]), "=r"(r[3]) : "r"(a));
}
__device__ __forceinline__ void mma_16816(float* d, const uint32_t* a, const uint32_t* b) {
    asm volatile("mma.sync.aligned.m16n8k16.row.col.f32.bf16.bf16.f32 "
        "{%0,%1,%2,%3}, {%4,%5,%6,%7}, {%8,%9}, {%0,%1,%2,%3};"
        : "+f"(d[0]), "+f"(d[1]), "+f"(d[2]), "+f"(d[3])
        : "r"(a[0]), "r"(a[1]), "r"(a[2]), "r"(a[3]), "r"(b[0]), "r"(b[1]));
}

// ---------------------------------------------------------------------------
// Kernel A: x -> (xh, xl) bf16 hi/lo split (layout preserved).
// ---------------------------------------------------------------------------
__global__ __launch_bounds__(256) void convert_x(const float* __restrict__ x) {
    const int i = (blockIdx.x * 256 + threadIdx.x) * 4;  // 262144 elems
    float4 v = *(const float4*)(x + i);
    float f[4] = {v.x, v.y, v.z, v.w};
    __nv_bfloat16 h[4], l[4];
#pragma unroll
    for (int q = 0; q < 4; q++) {
        h[q] = __float2bfloat16(f[q]);
        l[q] = __float2bfloat16(f[q] - __bfloat162float(h[q]));
    }
    ((__nv_bfloat162*)(g_xh + i))[0] = {h[0], h[1]};
    ((__nv_bfloat162*)(g_xh + i))[1] = {h[2], h[3]};
    ((__nv_bfloat162*)(g_xl + i))[0] = {l[0], l[1]};
    ((__nv_bfloat162*)(g_xl + i))[1] = {l[2], l[3]};
}

// ---------------------------------------------------------------------------
// Kernel B: W -> (Wh, Wl) bf16 hi/lo split, elementwise, native [k][n] layout.
// ---------------------------------------------------------------------------
__global__ __launch_bounds__(256) void convert_W(const float* __restrict__ W) {
    const size_t i = ((size_t)blockIdx.x * 256 + threadIdx.x) * 4;  // 4M elems
    float4 v = *(const float4*)(W + i);
    float f[4] = {v.x, v.y, v.z, v.w};
    __nv_bfloat16 h[4], l[4];
#pragma unroll
    for (int q = 0; q < 4; q++) {
        h[q] = __float2bfloat16(f[q]);
        l[q] = __float2bfloat16(f[q] - __bfloat162float(h[q]));
    }
    ((__nv_bfloat162*)(g_Wh + i))[0] = {h[0], h[1]};
    ((__nv_bfloat162*)(g_Wh + i))[1] = {h[2], h[3]};
    ((__nv_bfloat162*)(g_Wl + i))[0] = {l[0], l[1]};
    ((__nv_bfloat162*)(g_Wl + i))[1] = {l[2], l[3]};
}

// ---------------------------------------------------------------------------
// Kernel C: bf16 HMMA GEMM, 3-term compensated: M = xh*Wh + xl*Wh + xh*Wl.
// CTA tile 128(m) x 64(n), BK=64; 8 warps (warp tile 32x32); double-buffered
// cp.async; A smem [m][k] (128B rows), B smem [k][n] (128B rows), SW128.
// Grid (JDIM/64, NB/128) = (64, 2) = 128 CTAs.
// ---------------------------------------------------------------------------
#define BM 128
#define BN 64
#define BK 64
#define NSTEP 48   // 3 phases x (1024/64)

#define OFF_A0 0
#define OFF_A1 16384
#define OFF_B0 32768
#define OFF_B1 40960

__global__ __launch_bounds__(256) void gemm_kernel() {
    __shared__ __align__(1024) char smem[49152];
    const uint32_t sbase = smem_u32(smem);
    const int tid = threadIdx.x;
    const int wid = tid >> 5;
    const int lane = tid & 31;
    const int m0 = blockIdx.y * BM;
    const int n0 = blockIdx.x * BN;
    const int wm = (wid >> 1) * 32;   // warp m offset
    const int wn = (wid & 1) * 32;    // warp n offset

    const __nv_bfloat16* Asrc[3] = {g_xh, g_xl, g_xh};
    const __nv_bfloat16* Bsrc[3] = {g_Wh, g_Wh, g_Wl};

    // load mapping: A 1024 16B-chunks (4/thr), B 512 chunks (2/thr)
    const int a_row[4] = {(tid + 0) >> 3, (tid + 256) >> 3, (tid + 512) >> 3, (tid + 768) >> 3};
    const int a_c = tid & 7;
    const int b_row[2] = {(tid + 0) >> 3, (tid + 256) >> 3};

    auto issue_loads = [&](int t, int buf) {
        const int p = t >> 4;
        const int kk = (t & 15) * BK;
        const __nv_bfloat16* A = Asrc[p];
        const __nv_bfloat16* B = Bsrc[p];
        const uint32_t Ab = sbase + (buf ? OFF_A1 : OFF_A0);
        const uint32_t Bb = sbase + (buf ? OFF_B1 : OFF_B0);
#pragma unroll
        for (int q = 0; q < 4; q++) {
            const int r = a_row[q];
            cp16(Ab + SWZ(r * 128 + a_c * 16),
                 A + (size_t)(m0 + r) * IN_F + kk + a_c * 8);
        }
#pragma unroll
        for (int q = 0; q < 2; q++) {
            const int r = b_row[q];
            cp16(Bb + SWZ(r * 128 + a_c * 16),
                 B + (size_t)(kk + r) * JDIM + n0 + a_c * 8);
        }
    };

    float acc[2][4][4] = {};   // [m-tile][n8-tile][reg]

    issue_loads(0, 0);
    CP_COMMIT();

    for (int t = 0; t < NSTEP; t++) {
        if (t + 1 < NSTEP) issue_loads(t + 1, (t + 1) & 1);
        CP_COMMIT();
        CP_WAIT1();
        __syncthreads();

        const uint32_t Ab = sbase + ((t & 1) ? OFF_A1 : OFF_A0);
        const uint32_t Bb = sbase + ((t & 1) ? OFF_B1 : OFF_B0);

#pragma unroll
        for (int s = 0; s < 4; s++) {   // 4 x k16 per BK=64
            uint32_t af[2][4], bf[2][4];
#pragma unroll
            for (int mt = 0; mt < 2; mt++)
                ldsm_x4(af[mt], Ab + SWZ((wm + mt * 16 + (lane & 15)) * 128 +
                                         s * 32 + (lane >> 4) * 16));
#pragma unroll
            for (int nt = 0; nt < 2; nt++)
                ldsm_x4_t(bf[nt], Bb + SWZ((s * 16 + (lane & 15)) * 128 +
                                           (wn + nt * 16) * 2 + (lane >> 4) * 16));
#pragma unroll
            for (int mt = 0; mt < 2; mt++)
#pragma unroll
                for (int j = 0; j < 4; j++)
                    mma_16816(acc[mt][j], af[mt], bf[j >> 1] + (j & 1) * 2);
        }
        __syncthreads();
    }

    // epilogue: write fp32 tiles to g_M
    const int g = lane >> 2, tig = lane & 3;
#pragma unroll
    for (int mt = 0; mt < 2; mt++) {
#pragma unroll
        for (int j = 0; j < 4; j++) {
            const size_t base = (size_t)(m0 + wm + mt * 16 + g) * JDIM +
                                n0 + wn + j * 8 + tig * 2;
            *(float2*)(g_M + base)             = make_float2(acc[mt][j][0], acc[mt][j][1]);
            *(float2*)(g_M + base + 8 * JDIM)  = make_float2(acc[mt][j][2], acc[mt][j][3]);
        }
    }
}

// ---------------------------------------------------------------------------
// Kernel D: pairwise L1 + exp-sum (scalar; fabs is free FADD modifier)
// with folded x-copy. Grid = 256 blocks (one per b), 256 threads (one per m).
// ---------------------------------------------------------------------------
__global__ __launch_bounds__(256) void pairwise_kernel(const float* __restrict__ x,
                                                       float* __restrict__ out) {
    __shared__ float sM[NB][KDIM];
    const int b = blockIdx.x;
    const int tid = threadIdx.x;

    // folded x-copy: one float4 per thread
    {
        const int gidx = b * 256 + tid;
        const int row = gidx >> 8;
        const int c = gidx & 255;
        ((float4*)(out + (size_t)row * OUT_F))[c] =
            ((const float4*)(x + (size_t)row * IN_F))[c];
    }

    // load M[:, b, :] (256 x 16)
    const float4* Mg = (const float4*)g_M;
    float4* sM4 = (float4*)sM;
#pragma unroll
    for (int p = 0; p < 4; p++) {
        const int idx = tid + p * 256;
        const int row = idx >> 2;
        const int q = idx & 3;
        sM4[row * 4 + q] = Mg[(size_t)row * (JDIM / 4) + b * 4 + q];
    }
    __syncthreads();

    float my[KDIM];
#pragma unroll
    for (int k = 0; k < KDIM; k++) my[k] = sM[tid][k];

    float acc = 0.0f;
#pragma unroll 4
    for (int n = 0; n < NB; n++) {
        float l1 = 0.0f;
#pragma unroll
        for (int k = 0; k < KDIM; k++)
            l1 += fabsf(sM[n][k] - my[k]);
        acc += __expf(-l1);
    }

    out[(size_t)tid * OUT_F + IN_F + b] = acc - 1.0f;
}

extern "C" void kernel_launch(void* const* d_in, const int* in_sizes, int n_in,
                              void* d_out, int out_size) {
    const float* x = (const float*)d_in[0];   // (256, 1024)
    const float* T = (const float*)d_in[1];   // (1024, 256, 16) == W[k][n]
    float* out = (float*)d_out;               // (256, 1280)

    convert_x<<<256, 256>>>(x);
    convert_W<<<(IN_F * JDIM) / (256 * 4), 256>>>(T);

    gemm_kernel<<<dim3(JDIM / BN, NB / BM), 256>>>();

    pairwise_kernel<<<B_EXTRA, NB>>>(x, out);
}

// round 5
// speedup vs baseline: 1.9895x; 1.2117x over previous
#include <cuda_runtime.h>
#include <cuda_bf16.h>
#include <cuda_fp16.h>
#include <cstdint>

#define NB 256
#define IN_F 1024
#define B_EXTRA 256
#define KDIM 16
#define OUT_F 1280
#define JDIM 4096            // B_EXTRA * KDIM

// ---------------- device scratch ----------------
__device__ float g_M[NB * JDIM];                        // 4 MB
__device__ __nv_bfloat16 g_xh[NB * IN_F];               // [m][k]
__device__ __nv_bfloat16 g_xl[NB * IN_F];

// ---------------- helpers ----------------
__device__ __forceinline__ uint32_t smem_u32(const void* p) {
    uint32_t a;
    asm("{ .reg .u64 t; cvta.to.shared.u64 t, %1; cvt.u32.u64 %0, t; }" : "=r"(a) : "l"(p));
    return a;
}
#define SWZ(x) ((x) ^ (((x) >> 3) & 0x70))

__device__ __forceinline__ void cp16(uint32_t dst, const void* src) {
    asm volatile("cp.async.cg.shared.global [%0], [%1], 16;" :: "r"(dst), "l"(src) : "memory");
}
#define CP_COMMIT() asm volatile("cp.async.commit_group;" ::: "memory")
#define CP_WAIT0()  asm volatile("cp.async.wait_group 0;" ::: "memory")

__device__ __forceinline__ void ldsm_x4(uint32_t* r, uint32_t a) {
    asm volatile("ldmatrix.sync.aligned.m8n8.x4.shared.b16 {%0,%1,%2,%3}, [%4];"
        : "=r"(r[0]), "=r"(r[1]), "=r"(r[2]), "=r"(r[3]) : "r"(a));
}
__device__ __forceinline__ void ldsm_x4_t(uint32_t* r, uint32_t a) {
    asm volatile("ldmatrix.sync.aligned.m8n8.x4.trans.shared.b16 {%0,%1,%2,%3}, [%4];"
        : "=r"(r[0]), "=r"(r[1]), "=r"(r[2]), "=r"(r[3]) : "r"(a));
}
__device__ __forceinline__ void mma_16816(float* d, const uint32_t* a, const uint32_t* b) {
    asm volatile("mma.sync.aligned.m16n8k16.row.col.f32.bf16.bf16.f32 "
        "{%0,%1,%2,%3}, {%4,%5,%6,%7}, {%8,%9}, {%0,%1,%2,%3};"
        : "+f"(d[0]), "+f"(d[1]), "+f"(d[2]), "+f"(d[3])
        : "r"(a[0]), "r"(a[1]), "r"(a[2]), "r"(a[3]), "r"(b[0]), "r"(b[1]));
}
// pack top-16 bits of two fp32 as bf16x2 (truncation split)
__device__ __forceinline__ uint32_t prmt_hi(float f0, float f1) {
    uint32_t d;
    asm("prmt.b32 %0, %1, %2, 0x7632;" : "=r"(d) : "r"(__float_as_uint(f0)), "r"(__float_as_uint(f1)));
    return d;
}
__device__ __forceinline__ float trunc_hi(float f) {
    return __uint_as_float(__float_as_uint(f) & 0xFFFF0000u);
}
__device__ __forceinline__ uint32_t cvt_bf16x2(float flo, float fhi) {
    uint32_t d;
    asm("cvt.rn.bf16x2.f32 %0, %1, %2;" : "=r"(d) : "f"(fhi), "f"(flo));
    return d;
}

// ---------------------------------------------------------------------------
// Kernel A: x -> (xh, xl) bf16 hi/lo split.
// ---------------------------------------------------------------------------
__global__ __launch_bounds__(256) void convert_x(const float* __restrict__ x) {
    const int i = (blockIdx.x * 256 + threadIdx.x) * 4;
    float4 v = *(const float4*)(x + i);
    float f[4] = {v.x, v.y, v.z, v.w};
    uint32_t h01 = prmt_hi(f[0], f[1]);
    uint32_t h23 = prmt_hi(f[2], f[3]);
    uint32_t l01 = cvt_bf16x2(f[0] - trunc_hi(f[0]), f[1] - trunc_hi(f[1]));
    uint32_t l23 = cvt_bf16x2(f[2] - trunc_hi(f[2]), f[3] - trunc_hi(f[3]));
    *(uint2*)(g_xh + i) = make_uint2(h01, h23);
    *(uint2*)(g_xl + i) = make_uint2(l01, l23);
}

// ---------------------------------------------------------------------------
// Kernel B: bf16 HMMA GEMM, 3-term: M = xh*Wh + xl*Wh + xh*Wl (one accum).
// W consumed as fp32 directly; hi/lo bf16 conversion done in-kernel.
// CTA 128(m) x 64(n), BK=64, 16 k-tiles, 8 warps (32x32 warp tiles),
// double-buffered smem (A via cp.async, W via LDG-reg prefetch + STS).
// Grid (64, 2) = 128 CTAs.
// ---------------------------------------------------------------------------
#define BM 128
#define BN 64
#define BK 64
#define NT_K 16

#define GS_AH(b) ((b) * 16384)
#define GS_AL(b) (32768 + (b) * 16384)
#define GS_BH(b) (65536 + (b) * 8192)
#define GS_BL(b) (81920 + (b) * 8192)
#define GEMM_SMEM 98304

__global__ __launch_bounds__(256) void gemm_kernel(const float* __restrict__ W) {
    extern __shared__ __align__(1024) char smem[];
    const uint32_t sbase = smem_u32(smem);
    const int tid = threadIdx.x;
    const int wid = tid >> 5;
    const int lane = tid & 31;
    const int m0 = blockIdx.y * BM;
    const int n0 = blockIdx.x * BN;
    const int wm = (wid >> 1) * 32;
    const int wn = (wid & 1) * 32;

    // A cp.async mapping: 1024 16B-chunks per matrix, 4 per thread
    const int a_c = tid & 7;
    // W LDG mapping: 64 rows x 64 cols fp32; 4 thr/row, 4 float4 each
    const int w_r = tid >> 2;
    const int w_cg = tid & 3;

    float4 wr[4];

    auto ldg_W = [&](int t) {
        const float* src = W + (size_t)(t * BK + w_r) * JDIM + n0 + w_cg * 16;
#pragma unroll
        for (int q = 0; q < 4; q++) wr[q] = *(const float4*)(src + q * 4);
    };
    auto cpasync_A = [&](int t, int buf) {
        const int kk = t * BK;
        const uint32_t AhB = sbase + GS_AH(buf);
        const uint32_t AlB = sbase + GS_AL(buf);
#pragma unroll
        for (int q = 0; q < 4; q++) {
            const int r = (tid + q * 256) >> 3;
            const uint32_t off = SWZ(r * 128 + a_c * 16);
            const size_t gsrc = (size_t)(m0 + r) * IN_F + kk + a_c * 8;
            cp16(AhB + off, g_xh + gsrc);
            cp16(AlB + off, g_xl + gsrc);
        }
    };
    auto cvt_sts_W = [&](int buf) {
        const uint32_t BhB = sbase + GS_BH(buf);
        const uint32_t BlB = sbase + GS_BL(buf);
#pragma unroll
        for (int c = 0; c < 2; c++) {
            const float4 u = wr[2 * c], v = wr[2 * c + 1];
            const float f[8] = {u.x, u.y, u.z, u.w, v.x, v.y, v.z, v.w};
            uint4 hi, lo;
            hi.x = prmt_hi(f[0], f[1]); hi.y = prmt_hi(f[2], f[3]);
            hi.z = prmt_hi(f[4], f[5]); hi.w = prmt_hi(f[6], f[7]);
            lo.x = cvt_bf16x2(f[0] - trunc_hi(f[0]), f[1] - trunc_hi(f[1]));
            lo.y = cvt_bf16x2(f[2] - trunc_hi(f[2]), f[3] - trunc_hi(f[3]));
            lo.z = cvt_bf16x2(f[4] - trunc_hi(f[4]), f[5] - trunc_hi(f[5]));
            lo.w = cvt_bf16x2(f[6] - trunc_hi(f[6]), f[7] - trunc_hi(f[7]));
            const uint32_t off = SWZ(w_r * 128 + w_cg * 32 + c * 16);
            *(uint4*)(smem + (BhB - sbase) + off) = hi;
            *(uint4*)(smem + (BlB - sbase) + off) = lo;
        }
    };

    float acc[2][4][4] = {};

    // prologue
    ldg_W(0);
    cpasync_A(0, 0);
    CP_COMMIT();
    cvt_sts_W(0);
    CP_WAIT0();
    __syncthreads();

    for (int t = 0; t < NT_K; t++) {
        const int p = t & 1;
        if (t + 1 < NT_K) {
            ldg_W(t + 1);
            cpasync_A(t + 1, p ^ 1);
            CP_COMMIT();
        }

        const uint32_t AhB = sbase + GS_AH(p), AlB = sbase + GS_AL(p);
        const uint32_t BhB = sbase + GS_BH(p), BlB = sbase + GS_BL(p);
#pragma unroll
        for (int s = 0; s < 4; s++) {
            uint32_t ah[2][4], al[2][4], bh[2][4], bl[2][4];
#pragma unroll
            for (int mt = 0; mt < 2; mt++) {
                const uint32_t aoff = SWZ((wm + mt * 16 + (lane & 15)) * 128 +
                                          s * 32 + (lane >> 4) * 16);
                ldsm_x4(ah[mt], AhB + aoff);
                ldsm_x4(al[mt], AlB + aoff);
            }
#pragma unroll
            for (int nt = 0; nt < 2; nt++) {
                const uint32_t boff = SWZ((s * 16 + (lane & 15)) * 128 +
                                          (wn + nt * 16) * 2 + (lane >> 4) * 16);
                ldsm_x4_t(bh[nt], BhB + boff);
                ldsm_x4_t(bl[nt], BlB + boff);
            }
#pragma unroll
            for (int mt = 0; mt < 2; mt++)
#pragma unroll
                for (int j = 0; j < 4; j++) {
                    const uint32_t* bhj = bh[j >> 1] + (j & 1) * 2;
                    const uint32_t* blj = bl[j >> 1] + (j & 1) * 2;
                    mma_16816(acc[mt][j], ah[mt], bhj);
                    mma_16816(acc[mt][j], al[mt], bhj);
                    mma_16816(acc[mt][j], ah[mt], blj);
                }
        }

        if (t + 1 < NT_K) {
            cvt_sts_W(p ^ 1);
            CP_WAIT0();
        }
        __syncthreads();
    }

    // epilogue
    const int g = lane >> 2, tig = lane & 3;
#pragma unroll
    for (int mt = 0; mt < 2; mt++)
#pragma unroll
        for (int j = 0; j < 4; j++) {
            const size_t base = (size_t)(m0 + wm + mt * 16 + g) * JDIM +
                                n0 + wn + j * 8 + tig * 2;
            *(float2*)(g_M + base)            = make_float2(acc[mt][j][0], acc[mt][j][1]);
            *(float2*)(g_M + base + 8 * JDIM) = make_float2(acc[mt][j][2], acc[mt][j][3]);
        }
}

// ---------------------------------------------------------------------------
// Kernel C: pairwise L1 + exp-sum in fp16 half2 (k-dim packed, 2 lanes/op)
// with folded x-copy. Grid = 256 blocks (one per b), 256 threads (one per m).
// ---------------------------------------------------------------------------
__global__ __launch_bounds__(256) void pairwise_kernel(const float* __restrict__ x,
                                                       float* __restrict__ out) {
    __shared__ __align__(16) __half2 sH[NB][8];   // 8 KB, row = 32 B
    const int b = blockIdx.x;
    const int tid = threadIdx.x;

    // folded x-copy: one float4 per thread
    {
        const int gidx = b * 256 + tid;
        const int row = gidx >> 8;
        const int c = gidx & 255;
        ((float4*)(out + (size_t)row * OUT_F))[c] =
            ((const float4*)(x + (size_t)row * IN_F))[c];
    }

    // load M[:, b, :] (256 x 16 fp32) and convert to half2 (k packed)
    const float4* Mg = (const float4*)g_M;
#pragma unroll
    for (int p = 0; p < 4; p++) {
        const int idx = tid + p * 256;
        const int row = idx >> 2;
        const int q = idx & 3;
        float4 v = Mg[(size_t)row * (JDIM / 4) + b * 4 + q];
        sH[row][q * 2]     = __floats2half2_rn(v.x, v.y);
        sH[row][q * 2 + 1] = __floats2half2_rn(v.z, v.w);
    }
    __syncthreads();

    __half2 my[8];
#pragma unroll
    for (int k = 0; k < 8; k++) my[k] = sH[tid][k];

    float acc = 0.0f;
#pragma unroll 4
    for (int n = 0; n < NB; n++) {
        const __half2* r = sH[n];
        __half2 l1a = __habs2(__hsub2(r[0], my[0]));
        __half2 l1b = __habs2(__hsub2(r[1], my[1]));
#pragma unroll
        for (int k = 2; k < 8; k += 2) {
            l1a = __hadd2(l1a, __habs2(__hsub2(r[k], my[k])));
            l1b = __hadd2(l1b, __habs2(__hsub2(r[k + 1], my[k + 1])));
        }
        const __half2 l1 = __hadd2(l1a, l1b);
        const float l1f = __low2float(l1) + __high2float(l1);
        acc += __expf(-l1f);
    }

    out[(size_t)tid * OUT_F + IN_F + b] = acc - 1.0f;
}

extern "C" void kernel_launch(void* const* d_in, const int* in_sizes, int n_in,
                              void* d_out, int out_size) {
    const float* x = (const float*)d_in[0];   // (256, 1024)
    const float* T = (const float*)d_in[1];   // (1024, 256, 16) == W[k][n]
    float* out = (float*)d_out;               // (256, 1280)

    convert_x<<<256, 256>>>(x);

    cudaFuncSetAttribute(gemm_kernel, cudaFuncAttributeMaxDynamicSharedMemorySize, GEMM_SMEM);
    gemm_kernel<<<dim3(JDIM / BN, NB / BM), 256, GEMM_SMEM>>>(T);

    pairwise_kernel<<<B_EXTRA, NB>>>(x, out);
}

// round 6
// speedup vs baseline: 2.5256x; 1.2695x over previous
#include <cuda_runtime.h>
#include <cuda_bf16.h>
#include <cuda_fp16.h>
#include <cstdint>

#define NB 256
#define IN_F 1024
#define B_EXTRA 256
#define KDIM 16
#define OUT_F 1280
#define JDIM 4096            // B_EXTRA * KDIM

// ---------------- device scratch ----------------
__device__ float g_M[NB * JDIM];   // 4 MB

// ---------------- helpers ----------------
__device__ __forceinline__ uint32_t smem_u32(const void* p) {
    uint32_t a;
    asm("{ .reg .u64 t; cvta.to.shared.u64 t, %1; cvt.u32.u64 %0, t; }" : "=r"(a) : "l"(p));
    return a;
}
#define SWZ(x) ((x) ^ (((x) >> 3) & 0x70))

__device__ __forceinline__ void ldsm_x4(uint32_t* r, uint32_t a) {
    asm volatile("ldmatrix.sync.aligned.m8n8.x4.shared.b16 {%0,%1,%2,%3}, [%4];"
        : "=r"(r[0]), "=r"(r[1]), "=r"(r[2]), "=r"(r[3]) : "r"(a));
}
__device__ __forceinline__ void ldsm_x4_t(uint32_t* r, uint32_t a) {
    asm volatile("ldmatrix.sync.aligned.m8n8.x4.trans.shared.b16 {%0,%1,%2,%3}, [%4];"
        : "=r"(r[0]), "=r"(r[1]), "=r"(r[2]), "=r"(r[3]) : "r"(a));
}
__device__ __forceinline__ void mma_16816(float* d, const uint32_t* a, const uint32_t* b) {
    asm volatile("mma.sync.aligned.m16n8k16.row.col.f32.bf16.bf16.f32 "
        "{%0,%1,%2,%3}, {%4,%5,%6,%7}, {%8,%9}, {%0,%1,%2,%3};"
        : "+f"(d[0]), "+f"(d[1]), "+f"(d[2]), "+f"(d[3])
        : "r"(a[0]), "r"(a[1]), "r"(a[2]), "r"(a[3]), "r"(b[0]), "r"(b[1]));
}
// pack two fp32 -> bf16x2 (round-to-nearest), lo at low half
__device__ __forceinline__ uint32_t cvt_bf16x2(float flo, float fhi) {
    uint32_t d;
    asm("cvt.rn.bf16x2.f32 %0, %1, %2;" : "=r"(d) : "f"(fhi), "f"(flo));
    return d;
}

// ---------------------------------------------------------------------------
// Kernel A: bf16 HMMA GEMM, single term, fp32 inputs converted in-kernel.
//   M(256x4096) = bf16(x)(256x1024) @ bf16(W)(1024x4096), fp32 accum.
// CTA 128(m) x 64(n), BK=64, 16 k-tiles, 8 warps (32x32 warp tiles),
// double-buffered smem; A and B both LDG(fp32) -> cvt.rn.bf16x2 -> STS.
// Grid (64, 2) = 128 CTAs.
// ---------------------------------------------------------------------------
#define BM 128
#define BN 64
#define BK 64
#define NT_K 16

#define GS_A(b) ((b) * 16384)
#define GS_B(b) (32768 + (b) * 8192)

__global__ __launch_bounds__(256) void gemm_kernel(const float* __restrict__ x,
                                                   const float* __restrict__ W) {
    __shared__ __align__(1024) char smem[49152];
    const uint32_t sbase = smem_u32(smem);
    const int tid = threadIdx.x;
    const int wid = tid >> 5;
    const int lane = tid & 31;
    const int m0 = blockIdx.y * BM;
    const int n0 = blockIdx.x * BN;
    const int wm = (wid >> 1) * 32;
    const int wn = (wid & 1) * 32;

    // chunk mapping: idx -> (row = idx>>4, c4 = idx&15), 16 float4 per 64-elem row
    float4 ra[8];   // A: 128x64 fp32 = 2048 float4, 8 per thread
    float4 rb[4];   // B:  64x64 fp32 = 1024 float4, 4 per thread

    auto ldg_tiles = [&](int t) {
        const int kk = t * BK;
#pragma unroll
        for (int q = 0; q < 8; q++) {
            const int idx = tid + q * 256;
            ra[q] = *(const float4*)(x + (size_t)(m0 + (idx >> 4)) * IN_F + kk + (idx & 15) * 4);
        }
#pragma unroll
        for (int q = 0; q < 4; q++) {
            const int idx = tid + q * 256;
            rb[q] = *(const float4*)(W + (size_t)(kk + (idx >> 4)) * JDIM + n0 + (idx & 15) * 4);
        }
    };
    auto cvt_sts = [&](int buf) {
        char* A = smem + GS_A(buf);
        char* B = smem + GS_B(buf);
#pragma unroll
        for (int q = 0; q < 8; q++) {
            const int idx = tid + q * 256;
            const uint2 v = make_uint2(cvt_bf16x2(ra[q].x, ra[q].y),
                                       cvt_bf16x2(ra[q].z, ra[q].w));
            *(uint2*)(A + SWZ((idx >> 4) * 128 + (idx & 15) * 8)) = v;
        }
#pragma unroll
        for (int q = 0; q < 4; q++) {
            const int idx = tid + q * 256;
            const uint2 v = make_uint2(cvt_bf16x2(rb[q].x, rb[q].y),
                                       cvt_bf16x2(rb[q].z, rb[q].w));
            *(uint2*)(B + SWZ((idx >> 4) * 128 + (idx & 15) * 8)) = v;
        }
    };

    float acc[2][4][4] = {};

    // prologue
    ldg_tiles(0);
    cvt_sts(0);
    __syncthreads();

    for (int t = 0; t < NT_K; t++) {
        const int p = t & 1;
        if (t + 1 < NT_K) ldg_tiles(t + 1);   // prefetch overlaps the MMAs below

        const uint32_t Ab = sbase + GS_A(p);
        const uint32_t Bb = sbase + GS_B(p);
#pragma unroll
        for (int s = 0; s < 4; s++) {
            uint32_t af[2][4], bf[2][4];
#pragma unroll
            for (int mt = 0; mt < 2; mt++)
                ldsm_x4(af[mt], Ab + SWZ((wm + mt * 16 + (lane & 15)) * 128 +
                                         s * 32 + (lane >> 4) * 16));
#pragma unroll
            for (int nt = 0; nt < 2; nt++)
                ldsm_x4_t(bf[nt], Bb + SWZ((s * 16 + (lane & 15)) * 128 +
                                           (wn + nt * 16) * 2 + (lane >> 4) * 16));
#pragma unroll
            for (int mt = 0; mt < 2; mt++)
#pragma unroll
                for (int j = 0; j < 4; j++)
                    mma_16816(acc[mt][j], af[mt], bf[j >> 1] + (j & 1) * 2);
        }

        if (t + 1 < NT_K) cvt_sts(p ^ 1);
        __syncthreads();
    }

    // epilogue: write fp32 tiles to g_M
    const int g = lane >> 2, tig = lane & 3;
#pragma unroll
    for (int mt = 0; mt < 2; mt++)
#pragma unroll
        for (int j = 0; j < 4; j++) {
            const size_t base = (size_t)(m0 + wm + mt * 16 + g) * JDIM +
                                n0 + wn + j * 8 + tig * 2;
            *(float2*)(g_M + base)            = make_float2(acc[mt][j][0], acc[mt][j][1]);
            *(float2*)(g_M + base + 8 * JDIM) = make_float2(acc[mt][j][2], acc[mt][j][3]);
        }
}

// ---------------------------------------------------------------------------
// Kernel B: pairwise L1 + exp-sum in fp16 half2 (k-dim packed, 2 lanes/op)
// with folded x-copy. Grid = 256 blocks (one per b), 256 threads (one per m).
// ---------------------------------------------------------------------------
__global__ __launch_bounds__(256) void pairwise_kernel(const float* __restrict__ x,
                                                       float* __restrict__ out) {
    __shared__ __align__(16) __half2 sH[NB][8];   // 8 KB
    const int b = blockIdx.x;
    const int tid = threadIdx.x;

    // folded x-copy: one float4 per thread
    {
        const int gidx = b * 256 + tid;
        const int row = gidx >> 8;
        const int c = gidx & 255;
        ((float4*)(out + (size_t)row * OUT_F))[c] =
            ((const float4*)(x + (size_t)row * IN_F))[c];
    }

    // load M[:, b, :] (256 x 16 fp32) and convert to half2 (k packed)
    const float4* Mg = (const float4*)g_M;
#pragma unroll
    for (int p = 0; p < 4; p++) {
        const int idx = tid + p * 256;
        const int row = idx >> 2;
        const int q = idx & 3;
        float4 v = Mg[(size_t)row * (JDIM / 4) + b * 4 + q];
        sH[row][q * 2]     = __floats2half2_rn(v.x, v.y);
        sH[row][q * 2 + 1] = __floats2half2_rn(v.z, v.w);
    }
    __syncthreads();

    __half2 my[8];
#pragma unroll
    for (int k = 0; k < 8; k++) my[k] = sH[tid][k];

    float acc = 0.0f;
#pragma unroll 4
    for (int n = 0; n < NB; n++) {
        const __half2* r = sH[n];
        __half2 l1a = __habs2(__hsub2(r[0], my[0]));
        __half2 l1b = __habs2(__hsub2(r[1], my[1]));
#pragma unroll
        for (int k = 2; k < 8; k += 2) {
            l1a = __hadd2(l1a, __habs2(__hsub2(r[k], my[k])));
            l1b = __hadd2(l1b, __habs2(__hsub2(r[k + 1], my[k + 1])));
        }
        const __half2 l1 = __hadd2(l1a, l1b);
        const float l1f = __low2float(l1) + __high2float(l1);
        acc += __expf(-l1f);
    }

    out[(size_t)tid * OUT_F + IN_F + b] = acc - 1.0f;
}

extern "C" void kernel_launch(void* const* d_in, const int* in_sizes, int n_in,
                              void* d_out, int out_size) {
    const float* x = (const float*)d_in[0];   // (256, 1024)
    const float* T = (const float*)d_in[1];   // (1024, 256, 16) == W[k][n]
    float* out = (float*)d_out;               // (256, 1280)

    gemm_kernel<<<dim3(JDIM / BN, NB / BM), 256>>>(x, T);
    pairwise_kernel<<<B_EXTRA, NB>>>(x, out);
}

// round 7
// speedup vs baseline: 3.4892x; 1.3815x over previous
#include <cuda_runtime.h>
#include <cuda_bf16.h>
#include <cuda_fp16.h>
#include <cstdint>

#define NB 256
#define IN_F 1024
#define B_EXTRA 256
#define KDIM 16
#define OUT_F 1280
#define JDIM 4096            // B_EXTRA * KDIM

// ---------------- device scratch ----------------
__device__ float g_M[NB * JDIM];   // 4 MB

// ---------------- helpers ----------------
__device__ __forceinline__ uint32_t smem_u32(const void* p) {
    uint32_t a;
    asm("{ .reg .u64 t; cvta.to.shared.u64 t, %1; cvt.u32.u64 %0, t; }" : "=r"(a) : "l"(p));
    return a;
}
#define SWZ(x) ((x) ^ (((x) >> 3) & 0x70))

__device__ __forceinline__ void ldsm_x4(uint32_t* r, uint32_t a) {
    asm volatile("ldmatrix.sync.aligned.m8n8.x4.shared.b16 {%0,%1,%2,%3}, [%4];"
        : "=r"(r[0]), "=r"(r[1]), "=r"(r[2]), "=r"(r[3]) : "r"(a));
}
__device__ __forceinline__ void ldsm_x4_t(uint32_t* r, uint32_t a) {
    asm volatile("ldmatrix.sync.aligned.m8n8.x4.trans.shared.b16 {%0,%1,%2,%3}, [%4];"
        : "=r"(r[0]), "=r"(r[1]), "=r"(r[2]), "=r"(r[3]) : "r"(a));
}
__device__ __forceinline__ void mma_16816(float* d, const uint32_t* a, const uint32_t* b) {
    asm volatile("mma.sync.aligned.m16n8k16.row.col.f32.bf16.bf16.f32 "
        "{%0,%1,%2,%3}, {%4,%5,%6,%7}, {%8,%9}, {%0,%1,%2,%3};"
        : "+f"(d[0]), "+f"(d[1]), "+f"(d[2]), "+f"(d[3])
        : "r"(a[0]), "r"(a[1]), "r"(a[2]), "r"(a[3]), "r"(b[0]), "r"(b[1]));
}
__device__ __forceinline__ uint32_t cvt_bf16x2(float flo, float fhi) {
    uint32_t d;
    asm("cvt.rn.bf16x2.f32 %0, %1, %2;" : "=r"(d) : "f"(fhi), "f"(flo));
    return d;
}
// SIMD sum-of-absolute-differences over 4 signed bytes, with accumulate
__device__ __forceinline__ int vad4add(uint32_t a, uint32_t b, int c) {
    int d;
    asm("vabsdiff4.u32.s32.s32.add %0, %1, %2, %3;" : "=r"(d) : "r"(a), "r"(b), "r"(c));
    return d;
}
__device__ __forceinline__ float ex2f(float v) {
    float y;
    asm("ex2.approx.f32 %0, %1;" : "=f"(y) : "f"(v));
    return y;
}

// ---------------------------------------------------------------------------
// Kernel A: bf16 HMMA GEMM (unchanged from R6): M = bf16(x) @ bf16(W), fp32 acc.
// CTA 128x64, BK=64, 8 warps, double-buffered; in-kernel fp32->bf16 convert.
// ---------------------------------------------------------------------------
#define BM 128
#define BN 64
#define BK 64
#define NT_K 16

#define GS_A(b) ((b) * 16384)
#define GS_B(b) (32768 + (b) * 8192)

__global__ __launch_bounds__(256) void gemm_kernel(const float* __restrict__ x,
                                                   const float* __restrict__ W) {
    __shared__ __align__(1024) char smem[49152];
    const uint32_t sbase = smem_u32(smem);
    const int tid = threadIdx.x;
    const int wid = tid >> 5;
    const int lane = tid & 31;
    const int m0 = blockIdx.y * BM;
    const int n0 = blockIdx.x * BN;
    const int wm = (wid >> 1) * 32;
    const int wn = (wid & 1) * 32;

    float4 ra[8];
    float4 rb[4];

    auto ldg_tiles = [&](int t) {
        const int kk = t * BK;
#pragma unroll
        for (int q = 0; q < 8; q++) {
            const int idx = tid + q * 256;
            ra[q] = *(const float4*)(x + (size_t)(m0 + (idx >> 4)) * IN_F + kk + (idx & 15) * 4);
        }
#pragma unroll
        for (int q = 0; q < 4; q++) {
            const int idx = tid + q * 256;
            rb[q] = *(const float4*)(W + (size_t)(kk + (idx >> 4)) * JDIM + n0 + (idx & 15) * 4);
        }
    };
    auto cvt_sts = [&](int buf) {
        char* A = smem + GS_A(buf);
        char* B = smem + GS_B(buf);
#pragma unroll
        for (int q = 0; q < 8; q++) {
            const int idx = tid + q * 256;
            const uint2 v = make_uint2(cvt_bf16x2(ra[q].x, ra[q].y),
                                       cvt_bf16x2(ra[q].z, ra[q].w));
            *(uint2*)(A + SWZ((idx >> 4) * 128 + (idx & 15) * 8)) = v;
        }
#pragma unroll
        for (int q = 0; q < 4; q++) {
            const int idx = tid + q * 256;
            const uint2 v = make_uint2(cvt_bf16x2(rb[q].x, rb[q].y),
                                       cvt_bf16x2(rb[q].z, rb[q].w));
            *(uint2*)(B + SWZ((idx >> 4) * 128 + (idx & 15) * 8)) = v;
        }
    };

    float acc[2][4][4] = {};

    ldg_tiles(0);
    cvt_sts(0);
    __syncthreads();

    for (int t = 0; t < NT_K; t++) {
        const int p = t & 1;
        if (t + 1 < NT_K) ldg_tiles(t + 1);

        const uint32_t Ab = sbase + GS_A(p);
        const uint32_t Bb = sbase + GS_B(p);
#pragma unroll
        for (int s = 0; s < 4; s++) {
            uint32_t af[2][4], bf[2][4];
#pragma unroll
            for (int mt = 0; mt < 2; mt++)
                ldsm_x4(af[mt], Ab + SWZ((wm + mt * 16 + (lane & 15)) * 128 +
                                         s * 32 + (lane >> 4) * 16));
#pragma unroll
            for (int nt = 0; nt < 2; nt++)
                ldsm_x4_t(bf[nt], Bb + SWZ((s * 16 + (lane & 15)) * 128 +
                                           (wn + nt * 16) * 2 + (lane >> 4) * 16));
#pragma unroll
            for (int mt = 0; mt < 2; mt++)
#pragma unroll
                for (int j = 0; j < 4; j++)
                    mma_16816(acc[mt][j], af[mt], bf[j >> 1] + (j & 1) * 2);
        }

        if (t + 1 < NT_K) cvt_sts(p ^ 1);
        __syncthreads();
    }

    const int g = lane >> 2, tig = lane & 3;
#pragma unroll
    for (int mt = 0; mt < 2; mt++)
#pragma unroll
        for (int j = 0; j < 4; j++) {
            const size_t base = (size_t)(m0 + wm + mt * 16 + g) * JDIM +
                                n0 + wn + j * 8 + tig * 2;
            *(float2*)(g_M + base)            = make_float2(acc[mt][j][0], acc[mt][j][1]);
            *(float2*)(g_M + base + 8 * JDIM) = make_float2(acc[mt][j][2], acc[mt][j][3]);
        }
}

// ---------------------------------------------------------------------------
// Kernel B: pairwise L1 + exp-sum via int8 SIMD SAD (vabsdiff4.add).
// Per-block deterministic adaptive quantization: s = 127 / max|M[:,b,:]|.
// exp(-l1) = 2^(l1_int * negc), negc = -blockmax * log2(e) / 127.
// Grid = 256 blocks (one per b), 256 threads (one per m). Folded x-copy.
// ---------------------------------------------------------------------------
__global__ __launch_bounds__(256) void pairwise_kernel(const float* __restrict__ x,
                                                       float* __restrict__ out) {
    __shared__ __align__(16) uint4 sQ[NB];   // 4 KB: quantized rows
    __shared__ float sWmax[8];
    const int b = blockIdx.x;
    const int tid = threadIdx.x;
    const int lane = tid & 31;
    const int wid = tid >> 5;

    // folded x-copy: one float4 per thread
    {
        const int gidx = b * 256 + tid;
        const int row = gidx >> 8;
        const int c = gidx & 255;
        ((float4*)(out + (size_t)row * OUT_F))[c] =
            ((const float4*)(x + (size_t)row * IN_F))[c];
    }

    // each thread loads its own M row (16 fp32)
    const float* rowp = g_M + (size_t)tid * JDIM + b * KDIM;
    float f[16];
#pragma unroll
    for (int q = 0; q < 4; q++) {
        float4 v = ((const float4*)rowp)[q];
        f[4 * q] = v.x; f[4 * q + 1] = v.y; f[4 * q + 2] = v.z; f[4 * q + 3] = v.w;
    }

    // block max|.| (deterministic)
    float mx = fabsf(f[0]);
#pragma unroll
    for (int k = 1; k < 16; k++) mx = fmaxf(mx, fabsf(f[k]));
#pragma unroll
    for (int o = 16; o; o >>= 1) mx = fmaxf(mx, __shfl_xor_sync(0xFFFFFFFFu, mx, o));
    if (lane == 0) sWmax[wid] = mx;
    __syncthreads();
    float bm = sWmax[0];
#pragma unroll
    for (int w = 1; w < 8; w++) bm = fmaxf(bm, sWmax[w]);
    bm = fmaxf(bm, 1e-20f);

    // quantize own row to s8 and publish
    const float s = 127.0f / bm;
    uint32_t myq[4];
#pragma unroll
    for (int q = 0; q < 4; q++) {
        const int q0 = __float2int_rn(f[4 * q] * s);
        const int q1 = __float2int_rn(f[4 * q + 1] * s);
        const int q2 = __float2int_rn(f[4 * q + 2] * s);
        const int q3 = __float2int_rn(f[4 * q + 3] * s);
        myq[q] = (q0 & 255) | ((q1 & 255) << 8) | ((q2 & 255) << 16) | (q3 << 24);
    }
    sQ[tid] = make_uint4(myq[0], myq[1], myq[2], myq[3]);
    __syncthreads();

    const float negc = -bm * (1.44269504088896f / 127.0f);
    float acc0 = 0.0f, acc1 = 0.0f;

#pragma unroll 4
    for (int n = 0; n < NB; n += 2) {
        const uint4 qa = sQ[n];
        const uint4 qb = sQ[n + 1];
        int sa = vad4add(qa.x, myq[0], 0);
        int sb = vad4add(qb.x, myq[0], 0);
        int sa2 = vad4add(qa.y, myq[1], 0);
        int sb2 = vad4add(qb.y, myq[1], 0);
        sa = vad4add(qa.z, myq[2], sa);
        sb = vad4add(qb.z, myq[2], sb);
        sa2 = vad4add(qa.w, myq[3], sa2);
        sb2 = vad4add(qb.w, myq[3], sb2);
        acc0 += ex2f((float)(sa + sa2) * negc);
        acc1 += ex2f((float)(sb + sb2) * negc);
    }

    // self term exp(0)=1 subtracted per reference.
    out[(size_t)tid * OUT_F + IN_F + b] = (acc0 + acc1) - 1.0f;
}

extern "C" void kernel_launch(void* const* d_in, const int* in_sizes, int n_in,
                              void* d_out, int out_size) {
    const float* x = (const float*)d_in[0];   // (256, 1024)
    const float* T = (const float*)d_in[1];   // (1024, 256, 16) == W[k][n]
    float* out = (float*)d_out;               // (256, 1280)

    gemm_kernel<<<dim3(JDIM / BN, NB / BM), 256>>>(x, T);
    pairwise_kernel<<<B_EXTRA, NB>>>(x, out);
}

// round 8
// speedup vs baseline: 3.6620x; 1.0495x over previous
#include <cuda_runtime.h>
#include <cuda_bf16.h>
#include <cstdint>

#define NB 256
#define IN_F 1024
#define B_EXTRA 256
#define KDIM 16
#define OUT_F 1280
#define JDIM 4096            // B_EXTRA * KDIM

// ---------------- device scratch ----------------
__device__ float g_M[NB * JDIM];                       // 4 MB
__device__ __nv_bfloat16 g_xb[NB * IN_F];              // 512 KB [m][k]
__device__ __nv_bfloat16 g_Wb[(size_t)IN_F * JDIM];    // 8 MB  [k][n]

// ---------------- helpers ----------------
__device__ __forceinline__ uint32_t smem_u32(const void* p) {
    uint32_t a;
    asm("{ .reg .u64 t; cvta.to.shared.u64 t, %1; cvt.u32.u64 %0, t; }" : "=r"(a) : "l"(p));
    return a;
}
#define SWZ(x) ((x) ^ (((x) >> 3) & 0x70))

__device__ __forceinline__ void cp16(uint32_t dst, const void* src) {
    asm volatile("cp.async.cg.shared.global [%0], [%1], 16;" :: "r"(dst), "l"(src) : "memory");
}
#define CP_COMMIT() asm volatile("cp.async.commit_group;" ::: "memory")
#define CP_WAITG1() asm volatile("cp.async.wait_group 1;" ::: "memory")
#define CP_WAITG0() asm volatile("cp.async.wait_group 0;" ::: "memory")

__device__ __forceinline__ void ldsm_x4(uint32_t* r, uint32_t a) {
    asm volatile("ldmatrix.sync.aligned.m8n8.x4.shared.b16 {%0,%1,%2,%3}, [%4];"
        : "=r"(r[0]), "=r"(r[1]), "=r"(r[2]), "=r"(r[3]) : "r"(a));
}
__device__ __forceinline__ void ldsm_x4_t(uint32_t* r, uint32_t a) {
    asm volatile("ldmatrix.sync.aligned.m8n8.x4.trans.shared.b16 {%0,%1,%2,%3}, [%4];"
        : "=r"(r[0]), "=r"(r[1]), "=r"(r[2]), "=r"(r[3]) : "r"(a));
}
__device__ __forceinline__ void mma_16816(float* d, const uint32_t* a, const uint32_t* b) {
    asm volatile("mma.sync.aligned.m16n8k16.row.col.f32.bf16.bf16.f32 "
        "{%0,%1,%2,%3}, {%4,%5,%6,%7}, {%8,%9}, {%0,%1,%2,%3};"
        : "+f"(d[0]), "+f"(d[1]), "+f"(d[2]), "+f"(d[3])
        : "r"(a[0]), "r"(a[1]), "r"(a[2]), "r"(a[3]), "r"(b[0]), "r"(b[1]));
}
__device__ __forceinline__ uint32_t cvt_bf16x2(float flo, float fhi) {
    uint32_t d;
    asm("cvt.rn.bf16x2.f32 %0, %1, %2;" : "=r"(d) : "f"(fhi), "f"(flo));
    return d;
}
__device__ __forceinline__ int vad4add(uint32_t a, uint32_t b, int c) {
    int d;
    asm("vabsdiff4.u32.s32.s32.add %0, %1, %2, %3;" : "=r"(d) : "r"(a), "r"(b), "r"(c));
    return d;
}
__device__ __forceinline__ float ex2f(float v) {
    float y;
    asm("ex2.approx.f32 %0, %1;" : "=f"(y) : "f"(v));
    return y;
}

// ---------------------------------------------------------------------------
// Kernel 1: prep — W -> bf16 (blocks < 2048), x -> bf16 + x-copy (last 128).
// ---------------------------------------------------------------------------
__global__ __launch_bounds__(256) void prep_kernel(const float* __restrict__ x,
                                                   const float* __restrict__ W,
                                                   float* __restrict__ out) {
    const int blk = blockIdx.x;
    const int tid = threadIdx.x;
    if (blk < 2048) {
        const size_t i = ((size_t)blk * 256 + tid) * 8;   // 4M W elems, 8 each
        float4 u = *(const float4*)(W + i);
        float4 v = *(const float4*)(W + i + 4);
        uint4 o;
        o.x = cvt_bf16x2(u.x, u.y); o.y = cvt_bf16x2(u.z, u.w);
        o.z = cvt_bf16x2(v.x, v.y); o.w = cvt_bf16x2(v.z, v.w);
        *(uint4*)(g_Wb + i) = o;
    } else {
        const int j = (blk - 2048) * 256 + tid;           // 0..32767
        {   // x -> bf16: 8 elems each
            const size_t i = (size_t)j * 8;
            float4 u = *(const float4*)(x + i);
            float4 v = *(const float4*)(x + i + 4);
            uint4 o;
            o.x = cvt_bf16x2(u.x, u.y); o.y = cvt_bf16x2(u.z, u.w);
            o.z = cvt_bf16x2(v.x, v.y); o.w = cvt_bf16x2(v.z, v.w);
            *(uint4*)(g_xb + i) = o;
        }
        {   // x-copy into out[:, :1024]: 2 float4 each
#pragma unroll
            for (int p = 0; p < 2; p++) {
                const int g = j + p * 32768;              // 0..65535 float4s
                const int row = g >> 8;
                const int c = g & 255;
                ((float4*)(out + (size_t)row * OUT_F))[c] =
                    ((const float4*)(x + (size_t)row * IN_F))[c];
            }
        }
    }
}

// ---------------------------------------------------------------------------
// Kernel 2: bf16 HMMA GEMM, 3-stage cp.async pipeline, pure bf16 smem.
// CTA 128x64, BK=64, 8 warps (32x32 warp tiles). Grid (64, 2) = 128 CTAs.
// ---------------------------------------------------------------------------
#define BM 128
#define BN 64
#define BK 64
#define NT_K 16
#define STG_SZ 24576          // A 16KB + B 8KB
#define SA(s) ((s) * STG_SZ)
#define SB(s) ((s) * STG_SZ + 16384)
#define GEMM_SMEM (3 * STG_SZ)

__global__ __launch_bounds__(256) void gemm_kernel() {
    extern __shared__ __align__(1024) char smem[];
    const uint32_t sbase = smem_u32(smem);
    const int tid = threadIdx.x;
    const int wid = tid >> 5;
    const int lane = tid & 31;
    const int m0 = blockIdx.y * BM;
    const int n0 = blockIdx.x * BN;
    const int wm = (wid >> 1) * 32;
    const int wn = (wid & 1) * 32;

    // cp.async mapping: 16B chunks; A 1024 chunks (4/thr), B 512 (2/thr)
    const int c8 = tid & 7;   // chunk within 128B row

    auto issue_tile = [&](int t) {
        const int s = t % 3;
        const int kk = t * BK;
        const uint32_t Ab = sbase + SA(s);
        const uint32_t Bb = sbase + SB(s);
#pragma unroll
        for (int q = 0; q < 4; q++) {
            const int r = (tid + q * 256) >> 3;
            cp16(Ab + SWZ(r * 128 + c8 * 16),
                 g_xb + (size_t)(m0 + r) * IN_F + kk + c8 * 8);
        }
#pragma unroll
        for (int q = 0; q < 2; q++) {
            const int r = (tid + q * 256) >> 3;
            cp16(Bb + SWZ(r * 128 + c8 * 16),
                 g_Wb + (size_t)(kk + r) * JDIM + n0 + c8 * 8);
        }
        CP_COMMIT();
    };

    float acc[2][4][4] = {};

    issue_tile(0);
    issue_tile(1);

    for (int t = 0; t < NT_K; t++) {
        if (t + 2 < NT_K) CP_WAITG1(); else CP_WAITG0();
        __syncthreads();
        if (t + 2 < NT_K) issue_tile(t + 2);

        const int s = t % 3;
        const uint32_t Ab = sbase + SA(s);
        const uint32_t Bb = sbase + SB(s);
#pragma unroll
        for (int st = 0; st < 4; st++) {
            uint32_t af[2][4], bf[2][4];
#pragma unroll
            for (int mt = 0; mt < 2; mt++)
                ldsm_x4(af[mt], Ab + SWZ((wm + mt * 16 + (lane & 15)) * 128 +
                                         st * 32 + (lane >> 4) * 16));
#pragma unroll
            for (int nt = 0; nt < 2; nt++)
                ldsm_x4_t(bf[nt], Bb + SWZ((st * 16 + (lane & 15)) * 128 +
                                           (wn + nt * 16) * 2 + (lane >> 4) * 16));
#pragma unroll
            for (int mt = 0; mt < 2; mt++)
#pragma unroll
                for (int j = 0; j < 4; j++)
                    mma_16816(acc[mt][j], af[mt], bf[j >> 1] + (j & 1) * 2);
        }
        __syncthreads();
    }

    const int g = lane >> 2, tig = lane & 3;
#pragma unroll
    for (int mt = 0; mt < 2; mt++)
#pragma unroll
        for (int j = 0; j < 4; j++) {
            const size_t base = (size_t)(m0 + wm + mt * 16 + g) * JDIM +
                                n0 + wn + j * 8 + tig * 2;
            *(float2*)(g_M + base)            = make_float2(acc[mt][j][0], acc[mt][j][1]);
            *(float2*)(g_M + base + 8 * JDIM) = make_float2(acc[mt][j][2], acc[mt][j][3]);
        }
}

// ---------------------------------------------------------------------------
// Kernel 3: pairwise L1 + exp-sum via int8 SAD; 512 threads = (m, n-half).
// Grid = 256 blocks (one per b). Partials combined in smem, exact -1.
// ---------------------------------------------------------------------------
__global__ __launch_bounds__(512) void pairwise_kernel(float* __restrict__ out) {
    __shared__ __align__(16) uint4 sQ[NB];    // 4 KB quantized rows
    __shared__ float sWmax[8];
    __shared__ float sP[NB][2];               // 2 KB partials
    const int b = blockIdx.x;
    const int tid = threadIdx.x;
    const int m = tid & 255;
    const int half = tid >> 8;
    const int lane = tid & 31;
    const int wid = tid >> 5;

    // threads < 256: load own M row, block max, quantize, publish
    if (half == 0) {
        const float* rowp = g_M + (size_t)m * JDIM + b * KDIM;
        float f[16];
#pragma unroll
        for (int q = 0; q < 4; q++) {
            float4 v = ((const float4*)rowp)[q];
            f[4 * q] = v.x; f[4 * q + 1] = v.y; f[4 * q + 2] = v.z; f[4 * q + 3] = v.w;
        }
        float mx = fabsf(f[0]);
#pragma unroll
        for (int k = 1; k < 16; k++) mx = fmaxf(mx, fabsf(f[k]));
#pragma unroll
        for (int o = 16; o; o >>= 1) mx = fmaxf(mx, __shfl_xor_sync(0xFFFFFFFFu, mx, o));
        if (lane == 0) sWmax[wid] = mx;
        __syncthreads();
        float bm = sWmax[0];
#pragma unroll
        for (int w = 1; w < 8; w++) bm = fmaxf(bm, sWmax[w]);
        bm = fmaxf(bm, 1e-20f);
        const float s = 127.0f / bm;
        uint32_t q32[4];
#pragma unroll
        for (int q = 0; q < 4; q++) {
            const int q0 = __float2int_rn(f[4 * q] * s);
            const int q1 = __float2int_rn(f[4 * q + 1] * s);
            const int q2 = __float2int_rn(f[4 * q + 2] * s);
            const int q3 = __float2int_rn(f[4 * q + 3] * s);
            q32[q] = (q0 & 255) | ((q1 & 255) << 8) | ((q2 & 255) << 16) | (q3 << 24);
        }
        sQ[m] = make_uint4(q32[0], q32[1], q32[2], q32[3]);
    } else {
        __syncthreads();   // matches the reduction barrier above
    }
    __syncthreads();       // sQ published

    float bm = sWmax[0];
#pragma unroll
    for (int w = 1; w < 8; w++) bm = fmaxf(bm, sWmax[w]);
    bm = fmaxf(bm, 1e-20f);
    const float negc = -bm * (1.44269504088896f / 127.0f);

    const uint4 mq = sQ[m];
    const uint32_t myq0 = mq.x, myq1 = mq.y, myq2 = mq.z, myq3 = mq.w;

    float acc0 = 0.0f, acc1 = 0.0f;
    const int n0 = half * 128;
#pragma unroll 4
    for (int i = 0; i < 64; i++) {
        const int n = n0 + 2 * i;
        const uint4 qa = sQ[n];
        const uint4 qb = sQ[n + 1];
        int sa = vad4add(qa.x, myq0, 0);
        int sb = vad4add(qb.x, myq0, 0);
        int sa2 = vad4add(qa.y, myq1, 0);
        int sb2 = vad4add(qb.y, myq1, 0);
        sa = vad4add(qa.z, myq2, sa);
        sb = vad4add(qb.z, myq2, sb);
        sa2 = vad4add(qa.w, myq3, sa2);
        sb2 = vad4add(qb.w, myq3, sb2);
        acc0 += ex2f((float)(sa + sa2) * negc);
        acc1 += ex2f((float)(sb + sb2) * negc);
    }
    sP[m][half] = acc0 + acc1;
    __syncthreads();

    if (half == 0)
        out[(size_t)m * OUT_F + IN_F + b] = (sP[m][0] + sP[m][1]) - 1.0f;
}

extern "C" void kernel_launch(void* const* d_in, const int* in_sizes, int n_in,
                              void* d_out, int out_size) {
    const float* x = (const float*)d_in[0];   // (256, 1024)
    const float* T = (const float*)d_in[1];   // (1024, 256, 16) == W[k][n]
    float* out = (float*)d_out;               // (256, 1280)

    prep_kernel<<<2176, 256>>>(x, T, out);

    cudaFuncSetAttribute(gemm_kernel, cudaFuncAttributeMaxDynamicSharedMemorySize, GEMM_SMEM);
    gemm_kernel<<<dim3(JDIM / BN, NB / BM), 256, GEMM_SMEM>>>();

    pairwise_kernel<<<B_EXTRA, 512>>>(out);
}